// round 1
// baseline (speedup 1.0000x reference)
#include <cuda_runtime.h>
#include <math.h>

// Problem constants (from reference: x[16,64,256,256] f32, w[1,2,3,3] f32)
#define B_  16
#define C_  64
#define H_  256
#define W_  256
#define TH  32
#define TW  32
#define HH  (TH + 2)
#define HW_ (TW + 2)
#define NPIX (HH * HW_)          // 1156 halo pixels
#define NT  256
#define KPP ((NPIX + NT - 1) / NT)  // 5 halo pixels per thread

__global__ void __launch_bounds__(NT)
spatial_attention_kernel(const float* __restrict__ x,
                         const float* __restrict__ w,
                         float* __restrict__ out) {
    __shared__ float s_max[NPIX];
    __shared__ float s_avg[NPIX];
    __shared__ float s_attn[TH * TW];
    __shared__ float s_w[18];

    const int tid = threadIdx.x;
    const int b  = blockIdx.z;
    const int y0 = blockIdx.y * TH;
    const int x0 = blockIdx.x * TW;
    const float* __restrict__ xb = x + (size_t)b * C_ * H_ * W_;

    if (tid < 18) s_w[tid] = w[tid];

    // ---- Phase 1: channel mean+max over the 34x34 halo tile -------------
    int  off[KPP];
    bool val[KPP];
#pragma unroll
    for (int k = 0; k < KPP; k++) {
        int idx = tid + k * NT;
        val[k] = false; off[k] = 0;
        if (idx < NPIX) {
            int iy = idx / HW_;
            int ix = idx - iy * HW_;
            int Y = y0 - 1 + iy;
            int X = x0 - 1 + ix;
            if (Y >= 0 && Y < H_ && X >= 0 && X < W_) {
                val[k] = true;
                off[k] = Y * W_ + X;
            }
        }
    }

    float asum[KPP], amax[KPP];
#pragma unroll
    for (int k = 0; k < KPP; k++) { asum[k] = 0.0f; amax[k] = -1e30f; }

#pragma unroll 4
    for (int c = 0; c < C_; c++) {
        const float* __restrict__ xc = xb + (size_t)c * H_ * W_;
#pragma unroll
        for (int k = 0; k < KPP; k++) {
            if (val[k]) {
                float v = __ldg(xc + off[k]);   // default caching: re-read in phase 3
                asum[k] += v;
                amax[k] = fmaxf(amax[k], v);
            }
        }
    }

#pragma unroll
    for (int k = 0; k < KPP; k++) {
        int idx = tid + k * NT;
        if (idx < NPIX) {
            s_avg[idx] = val[k] ? asum[k] * (1.0f / C_) : 0.0f;  // zero padding for conv
            s_max[idx] = val[k] ? amax[k] : 0.0f;
        }
    }
    __syncthreads();

    // ---- Phase 2: 3x3 conv (concat order [max, avg]) + sigmoid ----------
#pragma unroll
    for (int k = 0; k < 4; k++) {
        int p  = tid + k * NT;         // 0..1023
        int y  = p >> 5;
        int xq = p & 31;
        float acc = 0.0f;
#pragma unroll
        for (int dy = 0; dy < 3; dy++) {
#pragma unroll
            for (int dx = 0; dx < 3; dx++) {
                int hi = (y + dy) * HW_ + (xq + dx);
                acc += s_w[dy * 3 + dx]     * s_max[hi];   // w[0,0,:,:] -> max
                acc += s_w[9 + dy * 3 + dx] * s_avg[hi];   // w[0,1,:,:] -> avg
            }
        }
        s_attn[p] = 1.0f / (1.0f + expf(-acc));
    }
    __syncthreads();

    // ---- Phase 3: broadcast multiply, float4 vectorized -----------------
    // Each thread owns 4 consecutive pixels in one row (32 % 4 == 0, aligned).
    const int p4 = tid * 4;
    const int y  = p4 >> 5;
    const int xq = p4 & 31;
    const size_t base = (size_t)(y0 + y) * W_ + (x0 + xq);
    const float4 a = *reinterpret_cast<const float4*>(&s_attn[p4]);
    float* __restrict__ ob = out + (size_t)b * C_ * H_ * W_;

#pragma unroll 4
    for (int c = 0; c < C_; c++) {
        const float4* src = reinterpret_cast<const float4*>(xb + (size_t)c * H_ * W_ + base);
        float4 v = __ldcs(src);          // last use: stream, don't pollute L2
        v.x *= a.x; v.y *= a.y; v.z *= a.z; v.w *= a.w;
        float4* dst = reinterpret_cast<float4*>(ob + (size_t)c * H_ * W_ + base);
        __stcs(dst, v);                  // streamed output: evict-first
    }
}

extern "C" void kernel_launch(void* const* d_in, const int* in_sizes, int n_in,
                              void* d_out, int out_size) {
    const float* x = (const float*)d_in[0];
    const float* w = (const float*)d_in[1];
    float* out     = (float*)d_out;

    dim3 grid(W_ / TW, H_ / TH, B_);   // (8, 8, 16) = 1024 blocks
    spatial_attention_kernel<<<grid, NT>>>(x, w, out);
}